// round 5
// baseline (speedup 1.0000x reference)
#include <cuda_runtime.h>
#include <cstdint>

#define NN 100000
#define EE 1000000
#define RR 1000
#define DD 100
#define D4 25
#define WPB 8        // warps per block (256 threads)
#define SLOT 80      // float4 per edge slot: [0,25)=E, [25,50)=R, [50,75)=rel, 75=nd, 76=sc
#define STAGE 160    // float4 per stage (2 edge slots)
#define NSTG 2       // pipeline depth in pair-stages

// ---------------- device scratch ------------------------------------------
__device__ int    g_row_ptr[NN + 1];
__device__ float4 g_rel_norm[RR * D4];
__device__ float4 g_relsc[2][RR];            // (rwE, rrE, rwR, rrR) per layer
__device__ float2 g_nd[2][NN];               // (ndotE, ndotR)
__device__ float4 g_feat0[NN * 50];          // interleaved E|R rows
__device__ float4 g_feat1[NN * 50];

// ---------------------------------------------------------------------------
__device__ __forceinline__ void wred2(float& a, float& b) {
#pragma unroll
    for (int o = 16; o; o >>= 1) {
        a += __shfl_xor_sync(0xffffffffu, a, o);
        b += __shfl_xor_sync(0xffffffffu, b, o);
    }
}
__device__ __forceinline__ void wred4(float& a, float& b, float& c, float& d) {
#pragma unroll
    for (int o = 16; o; o >>= 1) {
        a += __shfl_xor_sync(0xffffffffu, a, o);
        b += __shfl_xor_sync(0xffffffffu, b, o);
        c += __shfl_xor_sync(0xffffffffu, c, o);
        d += __shfl_xor_sync(0xffffffffu, d, o);
    }
}
__device__ __forceinline__ float dot4(float4 a, float4 b) {
    return a.x * b.x + a.y * b.y + a.z * b.z + a.w * b.w;
}
__device__ __forceinline__ void cp16(unsigned int s, const void* g) {
    asm volatile("cp.async.cg.shared.global [%0], [%1], 16;" :: "r"(s), "l"(g));
}
__device__ __forceinline__ void cp8(unsigned int s, const void* g) {
    asm volatile("cp.async.ca.shared.global [%0], [%1], 8;" :: "r"(s), "l"(g));
}
#define CP_COMMIT() asm volatile("cp.async.commit_group;" ::: "memory")
#define CP_WAIT(n)  asm volatile("cp.async.wait_group %0;" :: "n"(n) : "memory")

// ---------------- K0: row_ptr from sorted dst ------------------------------
__global__ void k_rowptr(const int* __restrict__ dst) {
    int n = blockIdx.x * blockDim.x + threadIdx.x;
    if (n > NN) return;
    int lo = 0, hi = EE;
    while (lo < hi) {
        int mid = (lo + hi) >> 1;
        if (dst[mid] < n) lo = mid + 1; else hi = mid;
    }
    g_row_ptr[n] = lo;
}

// ---------------- K1: relation norm + per-relation scalars -----------------
__global__ void k_rel(const float* __restrict__ rel_emb,
                      const float* __restrict__ attn_e,
                      const float* __restrict__ attn_r) {
    int warp = (blockIdx.x * blockDim.x + threadIdx.x) >> 5;
    int lane = threadIdx.x & 31;
    if (warp >= RR) return;

    float4 v = {0.f, 0.f, 0.f, 0.f};
    if (lane < D4) v = reinterpret_cast<const float4*>(rel_emb)[warp * D4 + lane];
    float ss = dot4(v, v), dummy = 0.f;
    wred2(ss, dummy);
    float inv = 1.f / fmaxf(sqrtf(ss), 1e-12f);
    v.x *= inv; v.y *= inv; v.z *= inv; v.w *= inv;
    if (lane < D4) g_rel_norm[warp * D4 + lane] = v;

#pragma unroll
    for (int c = 0; c < 4; c++) {   // c = enc*2 + layer
        const float* attn = (c < 2 ? attn_e : attn_r) + (c & 1) * (3 * DD);
        float4 wn = {0.f, 0.f, 0.f, 0.f}, wr = {0.f, 0.f, 0.f, 0.f};
        if (lane < D4) {
            wn = reinterpret_cast<const float4*>(attn + DD)[lane];
            wr = reinterpret_cast<const float4*>(attn + 2 * DD)[lane];
        }
        float dn = dot4(v, wn);
        float dr = dot4(v, wr);
        wred2(dn, dr);
        if (lane == 0) {
            int layer = c & 1;
            if (c < 2) { g_relsc[layer][warp].x = dn; g_relsc[layer][warp].y = dr; }
            else       { g_relsc[layer][warp].z = dn; g_relsc[layer][warp].w = dr; }
        }
    }
}

// ---------------- K2: initial segment means + tanh + ndot(layer 0) ---------
__global__ void __launch_bounds__(256)
k_init(const float* __restrict__ ent_emb,
       const float* __restrict__ rel_emb,
       const int* __restrict__ src,
       const int* __restrict__ erel,
       const float* __restrict__ attn_e,
       const float* __restrict__ attn_r,
       float* __restrict__ out) {
    int warp = (blockIdx.x * blockDim.x + threadIdx.x) >> 5;
    int lane = threadIdx.x & 31;
    if (warp >= NN) return;
    int beg = g_row_ptr[warp], end = g_row_ptr[warp + 1];
    bool act = lane < D4;

    const float4* ent4 = reinterpret_cast<const float4*>(ent_emb);
    const float4* rel4 = reinterpret_cast<const float4*>(rel_emb);
    float4 aE = {0,0,0,0}, aR = {0,0,0,0};
    float4 bE = {0,0,0,0}, bR = {0,0,0,0};
    int e = beg;
    for (; e + 3 < end; e += 4) {
        int s0 = src[e],   r0 = erel[e];
        int s1 = src[e+1], r1 = erel[e+1];
        int s2 = src[e+2], r2 = erel[e+2];
        int s3 = src[e+3], r3 = erel[e+3];
        if (act) {
            float4 a0 = ent4[s0*D4+lane], c0 = rel4[r0*D4+lane];
            float4 a1 = ent4[s1*D4+lane], c1 = rel4[r1*D4+lane];
            float4 a2 = ent4[s2*D4+lane], c2 = rel4[r2*D4+lane];
            float4 a3 = ent4[s3*D4+lane], c3 = rel4[r3*D4+lane];
            aE.x += a0.x + a1.x; aE.y += a0.y + a1.y; aE.z += a0.z + a1.z; aE.w += a0.w + a1.w;
            bE.x += a2.x + a3.x; bE.y += a2.y + a3.y; bE.z += a2.z + a3.z; bE.w += a2.w + a3.w;
            aR.x += c0.x + c1.x; aR.y += c0.y + c1.y; aR.z += c0.z + c1.z; aR.w += c0.w + c1.w;
            bR.x += c2.x + c3.x; bR.y += c2.y + c3.y; bR.z += c2.z + c3.z; bR.w += c2.w + c3.w;
        }
    }
    for (; e < end; e++) {
        int s0 = src[e], r0 = erel[e];
        if (act) {
            float4 a0 = ent4[s0*D4+lane], c0 = rel4[r0*D4+lane];
            aE.x += a0.x; aE.y += a0.y; aE.z += a0.z; aE.w += a0.w;
            aR.x += c0.x; aR.y += c0.y; aR.z += c0.z; aR.w += c0.w;
        }
    }
    aE.x += bE.x; aE.y += bE.y; aE.z += bE.z; aE.w += bE.w;
    aR.x += bR.x; aR.y += bR.y; aR.z += bR.z; aR.w += bR.w;

    float inv = 1.f / (float)max(end - beg, 1);
    float4 fE, fR;
    fE.x = tanhf(aE.x * inv); fE.y = tanhf(aE.y * inv);
    fE.z = tanhf(aE.z * inv); fE.w = tanhf(aE.w * inv);
    fR.x = tanhf(aR.x * inv); fR.y = tanhf(aR.y * inv);
    fR.z = tanhf(aR.z * inv); fR.w = tanhf(aR.w * inv);

    float4* out4 = reinterpret_cast<float4*>(out);
    if (act) {
        g_feat0[warp * 50 + lane]      = fE;
        g_feat0[warp * 50 + 25 + lane] = fR;
        out4[warp * 150 + lane]      = fE;
        out4[warp * 150 + 75 + lane] = fR;
    }

    float4 wnE = {0,0,0,0}, wnR = {0,0,0,0};
    if (act) {
        wnE = reinterpret_cast<const float4*>(attn_e + DD)[lane];
        wnR = reinterpret_cast<const float4*>(attn_r + DD)[lane];
    }
    float dE = dot4(fE, wnE);
    float dR = dot4(fR, wnR);
    wred2(dE, dR);
    if (lane == 0) g_nd[0][warp] = make_float2(dE, dR);
}

// ---------------- stage fill (cp.async) ------------------------------------
__device__ __forceinline__ void issue_pair(
    int e, float4* stage, int lane,
    const int* __restrict__ src, const int* __restrict__ erel,
    const float4* __restrict__ feat,
    const float2* __restrict__ nd, const float4* __restrict__ rsc) {
    int s0 = src[e],     r0 = erel[e];
    int s1 = src[e + 1], r1 = erel[e + 1];
    unsigned int sa = (unsigned int)__cvta_generic_to_shared(stage);
    if (lane < D4) {
        cp16(sa + (lane) * 16,              feat + (size_t)s0 * 50 + lane);
        cp16(sa + (25 + lane) * 16,         feat + (size_t)s0 * 50 + 25 + lane);
        cp16(sa + (50 + lane) * 16,         g_rel_norm + r0 * D4 + lane);
        cp16(sa + (SLOT + lane) * 16,       feat + (size_t)s1 * 50 + lane);
        cp16(sa + (SLOT + 25 + lane) * 16,  feat + (size_t)s1 * 50 + 25 + lane);
        cp16(sa + (SLOT + 50 + lane) * 16,  g_rel_norm + r1 * D4 + lane);
    } else if (lane == 25) cp8(sa + 75 * 16,          nd + s0);
    else if (lane == 26) cp16(sa + 76 * 16,           rsc + r0);
    else if (lane == 27) cp8(sa + (SLOT + 75) * 16,   nd + s1);
    else if (lane == 28) cp16(sa + (SLOT + 76) * 16,  rsc + r1);
    CP_COMMIT();
}

// ---------------- K3: one attention layer, cp.async pipelined --------------
template <int LAYER>
__global__ void __launch_bounds__(256, 4)
k_layer(const int* __restrict__ src,
        const int* __restrict__ erel,
        const float* __restrict__ attn_e,
        const float* __restrict__ attn_r,
        float* __restrict__ out) {
    __shared__ float4 sbuf[WPB][NSTG * STAGE];   // 40 KB
    int wib  = threadIdx.x >> 5;
    int warp = blockIdx.x * WPB + wib;
    int lane = threadIdx.x & 31;
    if (warp >= NN) return;
    int beg = g_row_ptr[warp], end = g_row_ptr[warp + 1];
    bool act = lane < D4;
    int li = min(lane, D4 - 1);   // clamped smem index: keeps lanes 25-31 in-bounds

    const float4* __restrict__ feat = (LAYER == 0) ? g_feat0 : g_feat1;
    const float2* __restrict__ nd   = g_nd[LAYER];
    const float4* __restrict__ rsc  = g_relsc[LAYER];
    float4* wsm = sbuf[wib];

    float ZE = 0.f, ZR = 0.f;
    float4 accE = {0,0,0,0};
    float4 accR = {0,0,0,0};

    int npairs = (end - beg) >> 1;
    int nfill = min(npairs, NSTG);
    for (int k = 0; k < nfill; k++)
        issue_pair(beg + 2 * k, wsm + k * STAGE, lane, src, erel, feat, nd, rsc);

    for (int ip = 0; ip < npairs; ip++) {
        if (npairs - ip >= 2) CP_WAIT(1); else CP_WAIT(0);
        __syncwarp();
        const float4* p0 = wsm + (ip & 1) * STAGE;
        const float4* p1 = p0 + SLOT;

        float4 fE0 = p0[li], fR0 = p0[25 + li], rv0 = p0[50 + li];
        float4 fE1 = p1[li], fR1 = p1[25 + li], rv1 = p1[50 + li];
        float2 nd0 = *reinterpret_cast<const float2*>(p0 + 75);
        float4 sc0 = p0[76];
        float2 nd1 = *reinterpret_cast<const float2*>(p1 + 75);
        float4 sc1 = p1[76];

        float pE0 = act ? dot4(fE0, rv0) : 0.f;
        float pR0 = act ? dot4(fR0, rv0) : 0.f;
        float pE1 = act ? dot4(fE1, rv1) : 0.f;
        float pR1 = act ? dot4(fR1, rv1) : 0.f;
        wred4(pE0, pR0, pE1, pR1);

        float wE0 = __expf(nd0.x - 2.f * pE0 * sc0.x + sc0.y);
        float wR0 = __expf(nd0.y - 2.f * pR0 * sc0.z + sc0.w);
        float wE1 = __expf(nd1.x - 2.f * pE1 * sc1.x + sc1.y);
        float wR1 = __expf(nd1.y - 2.f * pR1 * sc1.z + sc1.w);
        ZE += wE0 + wE1;
        ZR += wR0 + wR1;

        float bE0 = 2.f * wE0 * pE0, bR0 = 2.f * wR0 * pR0;
        float bE1 = 2.f * wE1 * pE1, bR1 = 2.f * wR1 * pR1;
        accE.x += wE0 * fE0.x - bE0 * rv0.x + wE1 * fE1.x - bE1 * rv1.x;
        accE.y += wE0 * fE0.y - bE0 * rv0.y + wE1 * fE1.y - bE1 * rv1.y;
        accE.z += wE0 * fE0.z - bE0 * rv0.z + wE1 * fE1.z - bE1 * rv1.z;
        accE.w += wE0 * fE0.w - bE0 * rv0.w + wE1 * fE1.w - bE1 * rv1.w;
        accR.x += wR0 * fR0.x - bR0 * rv0.x + wR1 * fR1.x - bR1 * rv1.x;
        accR.y += wR0 * fR0.y - bR0 * rv0.y + wR1 * fR1.y - bR1 * rv1.y;
        accR.z += wR0 * fR0.z - bR0 * rv0.z + wR1 * fR1.z - bR1 * rv1.z;
        accR.w += wR0 * fR0.w - bR0 * rv0.w + wR1 * fR1.w - bR1 * rv1.w;

        __syncwarp();
        int nx = ip + NSTG;
        if (nx < npairs)
            issue_pair(beg + 2 * nx, wsm + (ip & 1) * STAGE, lane,
                       src, erel, feat, nd, rsc);
    }

    // odd remaining edge: direct path
    if ((end - beg) & 1) {
        int e = end - 1;
        int s0 = src[e], r0 = erel[e];
        float4 fE0 = {0,0,0,0}, fR0 = {0,0,0,0}, rv0 = {0,0,0,0};
        if (act) {
            fE0 = feat[(size_t)s0 * 50 + lane];
            fR0 = feat[(size_t)s0 * 50 + 25 + lane];
            rv0 = g_rel_norm[r0 * D4 + lane];
        }
        float2 nd0 = nd[s0];
        float4 sc0 = rsc[r0];
        float pE0 = dot4(fE0, rv0), pR0 = dot4(fR0, rv0);
        wred2(pE0, pR0);
        float wE0 = __expf(nd0.x - 2.f * pE0 * sc0.x + sc0.y);
        float wR0 = __expf(nd0.y - 2.f * pR0 * sc0.z + sc0.w);
        ZE += wE0; ZR += wR0;
        float bE0 = 2.f * wE0 * pE0, bR0 = 2.f * wR0 * pR0;
        accE.x += wE0 * fE0.x - bE0 * rv0.x;
        accE.y += wE0 * fE0.y - bE0 * rv0.y;
        accE.z += wE0 * fE0.z - bE0 * rv0.z;
        accE.w += wE0 * fE0.w - bE0 * rv0.w;
        accR.x += wR0 * fR0.x - bR0 * rv0.x;
        accR.y += wR0 * fR0.y - bR0 * rv0.y;
        accR.z += wR0 * fR0.z - bR0 * rv0.z;
        accR.w += wR0 * fR0.w - bR0 * rv0.w;
    }

    float4 oE = {0,0,0,0}, oR = {0,0,0,0};
    if (end > beg) {
        float izE = 1.f / ZE, izR = 1.f / ZR;
        oE.x = tanhf(accE.x * izE); oE.y = tanhf(accE.y * izE);
        oE.z = tanhf(accE.z * izE); oE.w = tanhf(accE.w * izE);
        oR.x = tanhf(accR.x * izR); oR.y = tanhf(accR.y * izR);
        oR.z = tanhf(accR.z * izR); oR.w = tanhf(accR.w * izR);
    }

    float4* out4 = reinterpret_cast<float4*>(out);
    if (act) {
        out4[warp * 150 + (LAYER + 1) * D4 + lane]      = oE;
        out4[warp * 150 + 75 + (LAYER + 1) * D4 + lane] = oR;
        if (LAYER == 0) {
            g_feat1[warp * 50 + lane]      = oE;
            g_feat1[warp * 50 + 25 + lane] = oR;
        }
    }

    if (LAYER == 0) {
        float4 wnE = {0,0,0,0}, wnR = {0,0,0,0};
        if (act) {
            wnE = reinterpret_cast<const float4*>(attn_e + 3 * DD + DD)[lane];
            wnR = reinterpret_cast<const float4*>(attn_r + 3 * DD + DD)[lane];
        }
        float dE = dot4(oE, wnE);
        float dR = dot4(oR, wnR);
        wred2(dE, dR);
        if (lane == 0) g_nd[1][warp] = make_float2(dE, dR);
    }
}

// ---------------------------------------------------------------------------
extern "C" void kernel_launch(void* const* d_in, const int* in_sizes, int n_in,
                              void* d_out, int out_size) {
    const float* ent_emb = (const float*)d_in[0];
    const float* rel_emb = (const float*)d_in[1];
    const float* attn_e  = (const float*)d_in[2];
    const float* attn_r  = (const float*)d_in[3];
    const int*   src     = (const int*)d_in[4];
    const int*   dst     = (const int*)d_in[5];
    const int*   erel    = (const int*)d_in[6];
    float* out = (float*)d_out;

    k_rowptr<<<(NN + 1 + 255) / 256, 256>>>(dst);
    k_rel<<<(RR * 32 + 255) / 256, 256>>>(rel_emb, attn_e, attn_r);
    k_init<<<(NN * 32) / 256, 256>>>(ent_emb, rel_emb, src, erel,
                                     attn_e, attn_r, out);
    k_layer<0><<<(NN + WPB - 1) / WPB, 256>>>(src, erel, attn_e, attn_r, out);
    k_layer<1><<<(NN + WPB - 1) / WPB, 256>>>(src, erel, attn_e, attn_r, out);
}

// round 6
// speedup vs baseline: 1.0558x; 1.0558x over previous
#include <cuda_runtime.h>
#include <cstdint>

#define NN 100000
#define EE 1000000
#define RR 1000
#define DD 100
#define D4 25

// ---------------- device scratch (static; no allocations) ------------------
__device__ int    g_row_ptr[NN + 1];
__device__ float4 g_rel_norm[RR * D4];       // normalized relation embeddings
__device__ float4 g_relsc[2][RR];            // (-2rwE, rrE, -2rwR, rrR) per layer
__device__ float2 g_nd[2][NN];               // (ndotE, ndotR) per layer parity
__device__ float4 g_feat0[NN * 50];          // interleaved: [n*50+l]=E, [n*50+25+l]=R
__device__ float4 g_feat1[NN * 50];

// ---------------------------------------------------------------------------
__device__ __forceinline__ void wred2(float& a, float& b) {
#pragma unroll
    for (int o = 16; o; o >>= 1) {
        a += __shfl_xor_sync(0xffffffffu, a, o);
        b += __shfl_xor_sync(0xffffffffu, b, o);
    }
}
__device__ __forceinline__ void wred4(float& a, float& b, float& c, float& d) {
#pragma unroll
    for (int o = 16; o; o >>= 1) {
        a += __shfl_xor_sync(0xffffffffu, a, o);
        b += __shfl_xor_sync(0xffffffffu, b, o);
        c += __shfl_xor_sync(0xffffffffu, c, o);
        d += __shfl_xor_sync(0xffffffffu, d, o);
    }
}
__device__ __forceinline__ float dot4(float4 a, float4 b) {
    return a.x * b.x + a.y * b.y + a.z * b.z + a.w * b.w;
}

// ---------------- K0: row_ptr from sorted dst ------------------------------
__global__ void k_rowptr(const int* __restrict__ dst) {
    int n = blockIdx.x * blockDim.x + threadIdx.x;
    if (n > NN) return;
    int lo = 0, hi = EE;
    while (lo < hi) {
        int mid = (lo + hi) >> 1;
        if (dst[mid] < n) lo = mid + 1; else hi = mid;
    }
    g_row_ptr[n] = lo;
}

// ---------------- K1: relation normalization + per-relation scalars --------
__global__ void k_rel(const float* __restrict__ rel_emb,
                      const float* __restrict__ attn_e,
                      const float* __restrict__ attn_r) {
    int warp = (blockIdx.x * blockDim.x + threadIdx.x) >> 5;
    int lane = threadIdx.x & 31;
    if (warp >= RR) return;

    float4 v = {0.f, 0.f, 0.f, 0.f};
    if (lane < D4) v = reinterpret_cast<const float4*>(rel_emb)[warp * D4 + lane];
    float ss = dot4(v, v), dummy = 0.f;
    wred2(ss, dummy);
    float inv = 1.f / fmaxf(sqrtf(ss), 1e-12f);
    v.x *= inv; v.y *= inv; v.z *= inv; v.w *= inv;
    if (lane < D4) g_rel_norm[warp * D4 + lane] = v;

#pragma unroll
    for (int c = 0; c < 4; c++) {   // c = enc*2 + layer
        const float* attn = (c < 2 ? attn_e : attn_r) + (c & 1) * (3 * DD);
        float4 wn = {0.f, 0.f, 0.f, 0.f}, wr = {0.f, 0.f, 0.f, 0.f};
        if (lane < D4) {
            wn = reinterpret_cast<const float4*>(attn + DD)[lane];
            wr = reinterpret_cast<const float4*>(attn + 2 * DD)[lane];
        }
        float dn = dot4(v, wn);
        float dr = dot4(v, wr);
        wred2(dn, dr);
        if (lane == 0) {
            int layer = c & 1;
            // store -2*rw so logit arg = fmaf(p, sc.x, sc.y) + nd
            if (c < 2) { g_relsc[layer][warp].x = -2.f * dn; g_relsc[layer][warp].y = dr; }
            else       { g_relsc[layer][warp].z = -2.f * dn; g_relsc[layer][warp].w = dr; }
        }
    }
}

// ---------------- K2: initial segment means + tanh + ndot(layer 0) ---------
__global__ void __launch_bounds__(256)
k_init(const float* __restrict__ ent_emb,
       const float* __restrict__ rel_emb,
       const int* __restrict__ src,
       const int* __restrict__ erel,
       const float* __restrict__ attn_e,
       const float* __restrict__ attn_r,
       float* __restrict__ out) {
    int warp = (blockIdx.x * blockDim.x + threadIdx.x) >> 5;
    int lane = threadIdx.x & 31;
    if (warp >= NN) return;
    int beg = g_row_ptr[warp], end = g_row_ptr[warp + 1];
    bool act = lane < D4;

    const float4* ent4 = reinterpret_cast<const float4*>(ent_emb);
    const float4* rel4 = reinterpret_cast<const float4*>(rel_emb);
    float4 aE = {0,0,0,0}, aR = {0,0,0,0};
    float4 bE = {0,0,0,0}, bR = {0,0,0,0};
    int e = beg;
    for (; e + 3 < end; e += 4) {
        int s0 = src[e],   r0 = erel[e];
        int s1 = src[e+1], r1 = erel[e+1];
        int s2 = src[e+2], r2 = erel[e+2];
        int s3 = src[e+3], r3 = erel[e+3];
        if (act) {
            float4 a0 = ent4[s0*D4+lane], c0 = rel4[r0*D4+lane];
            float4 a1 = ent4[s1*D4+lane], c1 = rel4[r1*D4+lane];
            float4 a2 = ent4[s2*D4+lane], c2 = rel4[r2*D4+lane];
            float4 a3 = ent4[s3*D4+lane], c3 = rel4[r3*D4+lane];
            aE.x += a0.x + a1.x; aE.y += a0.y + a1.y; aE.z += a0.z + a1.z; aE.w += a0.w + a1.w;
            bE.x += a2.x + a3.x; bE.y += a2.y + a3.y; bE.z += a2.z + a3.z; bE.w += a2.w + a3.w;
            aR.x += c0.x + c1.x; aR.y += c0.y + c1.y; aR.z += c0.z + c1.z; aR.w += c0.w + c1.w;
            bR.x += c2.x + c3.x; bR.y += c2.y + c3.y; bR.z += c2.z + c3.z; bR.w += c2.w + c3.w;
        }
    }
    for (; e < end; e++) {
        int s0 = src[e], r0 = erel[e];
        if (act) {
            float4 a0 = ent4[s0*D4+lane], c0 = rel4[r0*D4+lane];
            aE.x += a0.x; aE.y += a0.y; aE.z += a0.z; aE.w += a0.w;
            aR.x += c0.x; aR.y += c0.y; aR.z += c0.z; aR.w += c0.w;
        }
    }
    aE.x += bE.x; aE.y += bE.y; aE.z += bE.z; aE.w += bE.w;
    aR.x += bR.x; aR.y += bR.y; aR.z += bR.z; aR.w += bR.w;

    float inv = 1.f / (float)max(end - beg, 1);
    float4 fE, fR;
    fE.x = tanhf(aE.x * inv); fE.y = tanhf(aE.y * inv);
    fE.z = tanhf(aE.z * inv); fE.w = tanhf(aE.w * inv);
    fR.x = tanhf(aR.x * inv); fR.y = tanhf(aR.y * inv);
    fR.z = tanhf(aR.z * inv); fR.w = tanhf(aR.w * inv);

    float4* out4 = reinterpret_cast<float4*>(out);
    if (act) {
        g_feat0[warp * 50 + lane]      = fE;
        g_feat0[warp * 50 + 25 + lane] = fR;
        out4[warp * 150 + lane]      = fE;
        out4[warp * 150 + 75 + lane] = fR;
    }

    float4 wnE = {0,0,0,0}, wnR = {0,0,0,0};
    if (act) {
        wnE = reinterpret_cast<const float4*>(attn_e + DD)[lane];
        wnR = reinterpret_cast<const float4*>(attn_r + DD)[lane];
    }
    float dE = dot4(fE, wnE);
    float dR = dot4(fR, wnR);
    wred2(dE, dR);
    if (lane == 0) g_nd[0][warp] = make_float2(dE, dR);
}

// ---------------- K3: one attention layer, both encoders, unroll-2 --------
template <int LAYER>
__global__ void __launch_bounds__(256, 5)
k_layer(const int* __restrict__ src,
        const int* __restrict__ erel,
        const float* __restrict__ attn_e,
        const float* __restrict__ attn_r,
        float* __restrict__ out) {
    int warp = (blockIdx.x * blockDim.x + threadIdx.x) >> 5;
    int lane = threadIdx.x & 31;
    if (warp >= NN) return;
    int beg = g_row_ptr[warp], end = g_row_ptr[warp + 1];

    const float4* __restrict__ feat = (LAYER == 0) ? g_feat0 : g_feat1;
    const float2* __restrict__ nd   = g_nd[LAYER];
    const float4* __restrict__ rsc  = g_relsc[LAYER];

    float ZE = 0.f, ZR = 0.f;
    float4 accE = {0,0,0,0};
    float4 accR = {0,0,0,0};
    bool act = lane < D4;

    int e = beg;
    for (; e + 1 < end; e += 2) {
        int s0 = src[e],     r0 = erel[e];
        int s1 = src[e + 1], r1 = erel[e + 1];
        float4 fE0 = {0,0,0,0}, fR0 = {0,0,0,0}, rv0 = {0,0,0,0};
        float4 fE1 = {0,0,0,0}, fR1 = {0,0,0,0}, rv1 = {0,0,0,0};
        if (act) {
            fE0 = feat[s0 * 50 + lane];
            fR0 = feat[s0 * 50 + 25 + lane];
            rv0 = g_rel_norm[r0 * D4 + lane];
            fE1 = feat[s1 * 50 + lane];
            fR1 = feat[s1 * 50 + 25 + lane];
            rv1 = g_rel_norm[r1 * D4 + lane];
        }
        float2 nd0 = nd[s0], nd1 = nd[s1];
        float4 sc0 = rsc[r0], sc1 = rsc[r1];

        float pE0 = dot4(fE0, rv0), pR0 = dot4(fR0, rv0);
        float pE1 = dot4(fE1, rv1), pR1 = dot4(fR1, rv1);
        wred4(pE0, pR0, pE1, pR1);

        float wE0 = __expf(nd0.x + fmaf(pE0, sc0.x, sc0.y));
        float wR0 = __expf(nd0.y + fmaf(pR0, sc0.z, sc0.w));
        float wE1 = __expf(nd1.x + fmaf(pE1, sc1.x, sc1.y));
        float wR1 = __expf(nd1.y + fmaf(pR1, sc1.z, sc1.w));
        ZE += wE0 + wE1;
        ZR += wR0 + wR1;

        float bE0 = 2.f * wE0 * pE0, bR0 = 2.f * wR0 * pR0;
        float bE1 = 2.f * wE1 * pE1, bR1 = 2.f * wR1 * pR1;
        accE.x += wE0 * fE0.x - bE0 * rv0.x + wE1 * fE1.x - bE1 * rv1.x;
        accE.y += wE0 * fE0.y - bE0 * rv0.y + wE1 * fE1.y - bE1 * rv1.y;
        accE.z += wE0 * fE0.z - bE0 * rv0.z + wE1 * fE1.z - bE1 * rv1.z;
        accE.w += wE0 * fE0.w - bE0 * rv0.w + wE1 * fE1.w - bE1 * rv1.w;
        accR.x += wR0 * fR0.x - bR0 * rv0.x + wR1 * fR1.x - bR1 * rv1.x;
        accR.y += wR0 * fR0.y - bR0 * rv0.y + wR1 * fR1.y - bR1 * rv1.y;
        accR.z += wR0 * fR0.z - bR0 * rv0.z + wR1 * fR1.z - bR1 * rv1.z;
        accR.w += wR0 * fR0.w - bR0 * rv0.w + wR1 * fR1.w - bR1 * rv1.w;
    }
    if (e < end) {
        int s0 = src[e], r0 = erel[e];
        float4 fE0 = {0,0,0,0}, fR0 = {0,0,0,0}, rv0 = {0,0,0,0};
        if (act) {
            fE0 = feat[s0 * 50 + lane];
            fR0 = feat[s0 * 50 + 25 + lane];
            rv0 = g_rel_norm[r0 * D4 + lane];
        }
        float2 nd0 = nd[s0];
        float4 sc0 = rsc[r0];
        float pE0 = dot4(fE0, rv0), pR0 = dot4(fR0, rv0);
        wred2(pE0, pR0);
        float wE0 = __expf(nd0.x + fmaf(pE0, sc0.x, sc0.y));
        float wR0 = __expf(nd0.y + fmaf(pR0, sc0.z, sc0.w));
        ZE += wE0; ZR += wR0;
        float bE0 = 2.f * wE0 * pE0, bR0 = 2.f * wR0 * pR0;
        accE.x += wE0 * fE0.x - bE0 * rv0.x;
        accE.y += wE0 * fE0.y - bE0 * rv0.y;
        accE.z += wE0 * fE0.z - bE0 * rv0.z;
        accE.w += wE0 * fE0.w - bE0 * rv0.w;
        accR.x += wR0 * fR0.x - bR0 * rv0.x;
        accR.y += wR0 * fR0.y - bR0 * rv0.y;
        accR.z += wR0 * fR0.z - bR0 * rv0.z;
        accR.w += wR0 * fR0.w - bR0 * rv0.w;
    }

    float4 oE = {0,0,0,0}, oR = {0,0,0,0};
    if (end > beg) {
        float izE = 1.f / ZE, izR = 1.f / ZR;
        oE.x = tanhf(accE.x * izE); oE.y = tanhf(accE.y * izE);
        oE.z = tanhf(accE.z * izE); oE.w = tanhf(accE.w * izE);
        oR.x = tanhf(accR.x * izR); oR.y = tanhf(accR.y * izR);
        oR.z = tanhf(accR.z * izR); oR.w = tanhf(accR.w * izR);
    }

    float4* out4 = reinterpret_cast<float4*>(out);
    if (act) {
        out4[warp * 150 + (LAYER + 1) * D4 + lane]      = oE;
        out4[warp * 150 + 75 + (LAYER + 1) * D4 + lane] = oR;
        if (LAYER == 0) {
            g_feat1[warp * 50 + lane]      = oE;
            g_feat1[warp * 50 + 25 + lane] = oR;
        }
    }

    if (LAYER == 0) {
        float4 wnE = {0,0,0,0}, wnR = {0,0,0,0};
        if (act) {
            wnE = reinterpret_cast<const float4*>(attn_e + 3 * DD + DD)[lane];
            wnR = reinterpret_cast<const float4*>(attn_r + 3 * DD + DD)[lane];
        }
        float dE = dot4(oE, wnE);
        float dR = dot4(oR, wnR);
        wred2(dE, dR);
        if (lane == 0) g_nd[1][warp] = make_float2(dE, dR);
    }
}

// ---------------------------------------------------------------------------
extern "C" void kernel_launch(void* const* d_in, const int* in_sizes, int n_in,
                              void* d_out, int out_size) {
    const float* ent_emb = (const float*)d_in[0];
    const float* rel_emb = (const float*)d_in[1];
    const float* attn_e  = (const float*)d_in[2];
    const float* attn_r  = (const float*)d_in[3];
    const int*   src     = (const int*)d_in[4];
    const int*   dst     = (const int*)d_in[5];
    const int*   erel    = (const int*)d_in[6];
    float* out = (float*)d_out;

    k_rowptr<<<(NN + 1 + 255) / 256, 256>>>(dst);
    k_rel<<<(RR * 32 + 255) / 256, 256>>>(rel_emb, attn_e, attn_r);
    k_init<<<(NN * 32) / 256, 256>>>(ent_emb, rel_emb, src, erel,
                                     attn_e, attn_r, out);
    k_layer<0><<<(NN * 32) / 256, 256>>>(src, erel, attn_e, attn_r, out);
    k_layer<1><<<(NN * 32) / 256, 256>>>(src, erel, attn_e, attn_r, out);
}

// round 7
// speedup vs baseline: 1.3196x; 1.2499x over previous
#include <cuda_runtime.h>
#include <cstdint>

#define NN 100000
#define EE 1000000
#define RR 1000
#define DD 100
#define D4 25
#define FSTR 64     // float4 per node row: 32 (E, padded) + 32 (R, padded)

// ---------------- device scratch (static; no allocations) ------------------
__device__ int    g_row_ptr[NN + 1];
__device__ float4 g_rel_norm[RR * 32];       // normalized rel embeddings, padded to 32 f4
__device__ float4 g_relsc[2][RR];            // (-2rwE, rrE, -2rwR, rrR) per layer
__device__ float2 g_nd[2][NN];               // (ndotE, ndotR) per layer parity
__device__ float4 g_feat0[NN * FSTR];        // padded interleaved E|R rows
__device__ float4 g_feat1[NN * FSTR];

// ---------------------------------------------------------------------------
__device__ __forceinline__ void wred2(float& a, float& b) {
#pragma unroll
    for (int o = 16; o; o >>= 1) {
        a += __shfl_xor_sync(0xffffffffu, a, o);
        b += __shfl_xor_sync(0xffffffffu, b, o);
    }
}
__device__ __forceinline__ float dot4(float4 a, float4 b) {
    return a.x * b.x + a.y * b.y + a.z * b.z + a.w * b.w;
}

// ---------------- K0: row_ptr from sorted dst ------------------------------
__global__ void k_rowptr(const int* __restrict__ dst) {
    int n = blockIdx.x * blockDim.x + threadIdx.x;
    if (n > NN) return;
    int lo = 0, hi = EE;
    while (lo < hi) {
        int mid = (lo + hi) >> 1;
        if (dst[mid] < n) lo = mid + 1; else hi = mid;
    }
    g_row_ptr[n] = lo;
}

// ---------------- K1: relation normalization + per-relation scalars --------
__global__ void k_rel(const float* __restrict__ rel_emb,
                      const float* __restrict__ attn_e,
                      const float* __restrict__ attn_r) {
    int warp = (blockIdx.x * blockDim.x + threadIdx.x) >> 5;
    int lane = threadIdx.x & 31;
    if (warp >= RR) return;

    float4 v = {0.f, 0.f, 0.f, 0.f};
    if (lane < D4) v = reinterpret_cast<const float4*>(rel_emb)[warp * D4 + lane];
    float ss = dot4(v, v), dummy = 0.f;
    wred2(ss, dummy);
    float inv = 1.f / fmaxf(sqrtf(ss), 1e-12f);
    v.x *= inv; v.y *= inv; v.z *= inv; v.w *= inv;
    // padded store: lanes 25-31 hold v = 0 already (guarded load)
    g_rel_norm[warp * 32 + lane] = v;

#pragma unroll
    for (int c = 0; c < 4; c++) {   // c = enc*2 + layer
        const float* attn = (c < 2 ? attn_e : attn_r) + (c & 1) * (3 * DD);
        float4 wn = {0.f, 0.f, 0.f, 0.f}, wr = {0.f, 0.f, 0.f, 0.f};
        if (lane < D4) {
            wn = reinterpret_cast<const float4*>(attn + DD)[lane];
            wr = reinterpret_cast<const float4*>(attn + 2 * DD)[lane];
        }
        float dn = dot4(v, wn);
        float dr = dot4(v, wr);
        wred2(dn, dr);
        if (lane == 0) {
            int layer = c & 1;
            if (c < 2) { g_relsc[layer][warp].x = -2.f * dn; g_relsc[layer][warp].y = dr; }
            else       { g_relsc[layer][warp].z = -2.f * dn; g_relsc[layer][warp].w = dr; }
        }
    }
}

// ---------------- K2: initial segment means + tanh + ndot(layer 0) ---------
__global__ void __launch_bounds__(256)
k_init(const float* __restrict__ ent_emb,
       const float* __restrict__ rel_emb,
       const int* __restrict__ src,
       const int* __restrict__ erel,
       const float* __restrict__ attn_e,
       const float* __restrict__ attn_r,
       float* __restrict__ out) {
    int warp = (blockIdx.x * blockDim.x + threadIdx.x) >> 5;
    int lane = threadIdx.x & 31;
    if (warp >= NN) return;
    int beg = g_row_ptr[warp], end = g_row_ptr[warp + 1];
    bool act = lane < D4;

    const float4* ent4 = reinterpret_cast<const float4*>(ent_emb);
    const float4* rel4 = reinterpret_cast<const float4*>(rel_emb);
    float4 aE = {0,0,0,0}, aR = {0,0,0,0};
    float4 bE = {0,0,0,0}, bR = {0,0,0,0};
    int e = beg;
    for (; e + 3 < end; e += 4) {
        int s0 = src[e],   r0 = erel[e];
        int s1 = src[e+1], r1 = erel[e+1];
        int s2 = src[e+2], r2 = erel[e+2];
        int s3 = src[e+3], r3 = erel[e+3];
        if (act) {
            float4 a0 = ent4[s0*D4+lane], c0 = rel4[r0*D4+lane];
            float4 a1 = ent4[s1*D4+lane], c1 = rel4[r1*D4+lane];
            float4 a2 = ent4[s2*D4+lane], c2 = rel4[r2*D4+lane];
            float4 a3 = ent4[s3*D4+lane], c3 = rel4[r3*D4+lane];
            aE.x += a0.x + a1.x; aE.y += a0.y + a1.y; aE.z += a0.z + a1.z; aE.w += a0.w + a1.w;
            bE.x += a2.x + a3.x; bE.y += a2.y + a3.y; bE.z += a2.z + a3.z; bE.w += a2.w + a3.w;
            aR.x += c0.x + c1.x; aR.y += c0.y + c1.y; aR.z += c0.z + c1.z; aR.w += c0.w + c1.w;
            bR.x += c2.x + c3.x; bR.y += c2.y + c3.y; bR.z += c2.z + c3.z; bR.w += c2.w + c3.w;
        }
    }
    for (; e < end; e++) {
        int s0 = src[e], r0 = erel[e];
        if (act) {
            float4 a0 = ent4[s0*D4+lane], c0 = rel4[r0*D4+lane];
            aE.x += a0.x; aE.y += a0.y; aE.z += a0.z; aE.w += a0.w;
            aR.x += c0.x; aR.y += c0.y; aR.z += c0.z; aR.w += c0.w;
        }
    }
    aE.x += bE.x; aE.y += bE.y; aE.z += bE.z; aE.w += bE.w;
    aR.x += bR.x; aR.y += bR.y; aR.z += bR.z; aR.w += bR.w;

    float inv = 1.f / (float)max(end - beg, 1);
    float4 fE, fR;
    fE.x = tanhf(aE.x * inv); fE.y = tanhf(aE.y * inv);
    fE.z = tanhf(aE.z * inv); fE.w = tanhf(aE.w * inv);
    fR.x = tanhf(aR.x * inv); fR.y = tanhf(aR.y * inv);
    fR.z = tanhf(aR.z * inv); fR.w = tanhf(aR.w * inv);
    // non-act lanes: aE/aR stayed 0 -> fE/fR = 0 -> padding written as zeros
    g_feat0[warp * FSTR + lane]      = fE;
    g_feat0[warp * FSTR + 32 + lane] = fR;

    float4* out4 = reinterpret_cast<float4*>(out);
    if (act) {
        out4[warp * 150 + lane]      = fE;
        out4[warp * 150 + 75 + lane] = fR;
    }

    float4 wnE = {0,0,0,0}, wnR = {0,0,0,0};
    if (act) {
        wnE = reinterpret_cast<const float4*>(attn_e + DD)[lane];
        wnR = reinterpret_cast<const float4*>(attn_r + DD)[lane];
    }
    float dE = dot4(fE, wnE);
    float dR = dot4(fR, wnR);
    wred2(dE, dR);
    if (lane == 0) g_nd[0][warp] = make_float2(dE, dR);
}

// ---------------- K3: attention layer, 2 edges/warp in 16-lane groups -----
template <int LAYER>
__global__ void __launch_bounds__(256)
k_layer(const int* __restrict__ src,
        const int* __restrict__ erel,
        const float* __restrict__ attn_e,
        const float* __restrict__ attn_r,
        float* __restrict__ out) {
    int warp = (blockIdx.x * blockDim.x + threadIdx.x) >> 5;
    int lane = threadIdx.x & 31;
    if (warp >= NN) return;
    int beg = g_row_ptr[warp], end = g_row_ptr[warp + 1];
    int len = end - beg;

    const float4* __restrict__ feat = (LAYER == 0) ? g_feat0 : g_feat1;
    const float2* __restrict__ nd   = g_nd[LAYER];
    const float4* __restrict__ rsc  = g_relsc[LAYER];

    int gid = lane >> 4;          // edge slot within iteration
    int k   = lane & 15;          // f4 chunk: covers f4 k and k+16

    float ZE = 0.f, ZR = 0.f;
    float4 accE0 = {0,0,0,0}, accE1 = {0,0,0,0};
    float4 accR0 = {0,0,0,0}, accR1 = {0,0,0,0};

    int niter = (len + 1) >> 1;
    for (int it = 0; it < niter; it++) {
        int e = beg + 2 * it + gid;
        bool valid = e < end;
        int ec = valid ? e : end - 1;
        int s = src[ec], r = erel[ec];

        const float4* fr = feat + (size_t)s * FSTR;
        const float4* rr = g_rel_norm + r * 32;
        float4 fE0 = fr[k],      fE1 = fr[k + 16];
        float4 fR0 = fr[32 + k], fR1 = fr[48 + k];
        float4 rv0 = rr[k],      rv1 = rr[k + 16];
        float2 ndv = nd[s];
        float4 sc  = rsc[r];

        float pE = dot4(fE0, rv0) + dot4(fE1, rv1);
        float pR = dot4(fR0, rv0) + dot4(fR1, rv1);
#pragma unroll
        for (int o = 1; o <= 8; o <<= 1) {
            pE += __shfl_xor_sync(0xffffffffu, pE, o);
            pR += __shfl_xor_sync(0xffffffffu, pR, o);
        }

        float wE = valid ? __expf(ndv.x + fmaf(pE, sc.x, sc.y)) : 0.f;
        float wR = valid ? __expf(ndv.y + fmaf(pR, sc.z, sc.w)) : 0.f;
        ZE += wE; ZR += wR;
        float bE = 2.f * wE * pE, bR = 2.f * wR * pR;

        accE0.x = fmaf(wE, fE0.x, fmaf(-bE, rv0.x, accE0.x));
        accE0.y = fmaf(wE, fE0.y, fmaf(-bE, rv0.y, accE0.y));
        accE0.z = fmaf(wE, fE0.z, fmaf(-bE, rv0.z, accE0.z));
        accE0.w = fmaf(wE, fE0.w, fmaf(-bE, rv0.w, accE0.w));
        accE1.x = fmaf(wE, fE1.x, fmaf(-bE, rv1.x, accE1.x));
        accE1.y = fmaf(wE, fE1.y, fmaf(-bE, rv1.y, accE1.y));
        accE1.z = fmaf(wE, fE1.z, fmaf(-bE, rv1.z, accE1.z));
        accE1.w = fmaf(wE, fE1.w, fmaf(-bE, rv1.w, accE1.w));
        accR0.x = fmaf(wR, fR0.x, fmaf(-bR, rv0.x, accR0.x));
        accR0.y = fmaf(wR, fR0.y, fmaf(-bR, rv0.y, accR0.y));
        accR0.z = fmaf(wR, fR0.z, fmaf(-bR, rv0.z, accR0.z));
        accR0.w = fmaf(wR, fR0.w, fmaf(-bR, rv0.w, accR0.w));
        accR1.x = fmaf(wR, fR1.x, fmaf(-bR, rv1.x, accR1.x));
        accR1.y = fmaf(wR, fR1.y, fmaf(-bR, rv1.y, accR1.y));
        accR1.z = fmaf(wR, fR1.z, fmaf(-bR, rv1.z, accR1.z));
        accR1.w = fmaf(wR, fR1.w, fmaf(-bR, rv1.w, accR1.w));
    }

    // cross-group combine (once per node): both groups end with full sums
    ZE += __shfl_xor_sync(0xffffffffu, ZE, 16);
    ZR += __shfl_xor_sync(0xffffffffu, ZR, 16);
    accE0.x += __shfl_xor_sync(0xffffffffu, accE0.x, 16);
    accE0.y += __shfl_xor_sync(0xffffffffu, accE0.y, 16);
    accE0.z += __shfl_xor_sync(0xffffffffu, accE0.z, 16);
    accE0.w += __shfl_xor_sync(0xffffffffu, accE0.w, 16);
    accE1.x += __shfl_xor_sync(0xffffffffu, accE1.x, 16);
    accE1.y += __shfl_xor_sync(0xffffffffu, accE1.y, 16);
    accE1.z += __shfl_xor_sync(0xffffffffu, accE1.z, 16);
    accE1.w += __shfl_xor_sync(0xffffffffu, accE1.w, 16);
    accR0.x += __shfl_xor_sync(0xffffffffu, accR0.x, 16);
    accR0.y += __shfl_xor_sync(0xffffffffu, accR0.y, 16);
    accR0.z += __shfl_xor_sync(0xffffffffu, accR0.z, 16);
    accR0.w += __shfl_xor_sync(0xffffffffu, accR0.w, 16);
    accR1.x += __shfl_xor_sync(0xffffffffu, accR1.x, 16);
    accR1.y += __shfl_xor_sync(0xffffffffu, accR1.y, 16);
    accR1.z += __shfl_xor_sync(0xffffffffu, accR1.z, 16);
    accR1.w += __shfl_xor_sync(0xffffffffu, accR1.w, 16);

    float4 oE0 = {0,0,0,0}, oE1 = {0,0,0,0}, oR0 = {0,0,0,0}, oR1 = {0,0,0,0};
    if (len > 0) {
        float izE = 1.f / ZE, izR = 1.f / ZR;
        oE0.x = tanhf(accE0.x * izE); oE0.y = tanhf(accE0.y * izE);
        oE0.z = tanhf(accE0.z * izE); oE0.w = tanhf(accE0.w * izE);
        oE1.x = tanhf(accE1.x * izE); oE1.y = tanhf(accE1.y * izE);
        oE1.z = tanhf(accE1.z * izE); oE1.w = tanhf(accE1.w * izE);
        oR0.x = tanhf(accR0.x * izR); oR0.y = tanhf(accR0.y * izR);
        oR0.z = tanhf(accR0.z * izR); oR0.w = tanhf(accR0.w * izR);
        oR1.x = tanhf(accR1.x * izR); oR1.y = tanhf(accR1.y * izR);
        oR1.z = tanhf(accR1.z * izR); oR1.w = tanhf(accR1.w * izR);
    }
    // padding dims: acc stayed 0 -> o = tanh(0) = 0, so stored padding stays zero

    // lane l covers output f4 index l: group 0 lanes use o*0 (f4 k), group 1 use o*1 (f4 k+16)
    float4 myE = gid ? oE1 : oE0;
    float4 myR = gid ? oR1 : oR0;

    float4* out4 = reinterpret_cast<float4*>(out);
    if (lane < D4) {
        out4[warp * 150 + (LAYER + 1) * D4 + lane]      = myE;
        out4[warp * 150 + 75 + (LAYER + 1) * D4 + lane] = myR;
    }
    if (LAYER == 0) {
        g_feat1[warp * FSTR + lane]      = myE;
        g_feat1[warp * FSTR + 32 + lane] = myR;

        // ndot for layer 1 (in-bounds reads: attn has 600 floats, max offset 527)
        const float4* wnE4 = reinterpret_cast<const float4*>(attn_e + 3 * DD + DD);
        const float4* wnR4 = reinterpret_cast<const float4*>(attn_r + 3 * DD + DD);
        float dE = dot4(oE0, wnE4[k]) + dot4(oE1, wnE4[k + 16]);
        float dR = dot4(oR0, wnR4[k]) + dot4(oR1, wnR4[k + 16]);
#pragma unroll
        for (int o = 1; o <= 8; o <<= 1) {
            dE += __shfl_xor_sync(0xffffffffu, dE, o);
            dR += __shfl_xor_sync(0xffffffffu, dR, o);
        }
        if (lane == 0) g_nd[1][warp] = make_float2(dE, dR);
    }
}

// ---------------------------------------------------------------------------
extern "C" void kernel_launch(void* const* d_in, const int* in_sizes, int n_in,
                              void* d_out, int out_size) {
    const float* ent_emb = (const float*)d_in[0];
    const float* rel_emb = (const float*)d_in[1];
    const float* attn_e  = (const float*)d_in[2];
    const float* attn_r  = (const float*)d_in[3];
    const int*   src     = (const int*)d_in[4];
    const int*   dst     = (const int*)d_in[5];
    const int*   erel    = (const int*)d_in[6];
    float* out = (float*)d_out;

    k_rowptr<<<(NN + 1 + 255) / 256, 256>>>(dst);
    k_rel<<<(RR * 32 + 255) / 256, 256>>>(rel_emb, attn_e, attn_r);
    k_init<<<(NN * 32) / 256, 256>>>(ent_emb, rel_emb, src, erel,
                                     attn_e, attn_r, out);
    k_layer<0><<<(NN * 32) / 256, 256>>>(src, erel, attn_e, attn_r, out);
    k_layer<1><<<(NN * 32) / 256, 256>>>(src, erel, attn_e, attn_r, out);
}

// round 8
// speedup vs baseline: 1.3307x; 1.0085x over previous
#include <cuda_runtime.h>
#include <cstdint>

#define NN 100000
#define EE 1000000
#define RR 1000
#define DD 100
#define D4 25
#define FSTR 50     // float4 per node row: 25 (E) + 25 (R), unpadded

// ---------------- device scratch (static; no allocations) ------------------
__device__ int    g_row_ptr[NN + 1];
__device__ float4 g_rel_norm[RR * D4];       // normalized rel embeddings (25 f4/row)
__device__ float4 g_relsc[2][RR];            // (-2rwE, rrE, -2rwR, rrR) per layer
__device__ float2 g_nd[2][NN];               // (ndotE, ndotR) per layer parity
__device__ float4 g_feat0[NN * FSTR];        // interleaved E|R rows
__device__ float4 g_feat1[NN * FSTR];

// ---------------------------------------------------------------------------
__device__ __forceinline__ void wred2(float& a, float& b) {
#pragma unroll
    for (int o = 16; o; o >>= 1) {
        a += __shfl_xor_sync(0xffffffffu, a, o);
        b += __shfl_xor_sync(0xffffffffu, b, o);
    }
}
__device__ __forceinline__ float dot4(float4 a, float4 b) {
    return a.x * b.x + a.y * b.y + a.z * b.z + a.w * b.w;
}

// ---------------- K0: row_ptr from sorted dst ------------------------------
__global__ void k_rowptr(const int* __restrict__ dst) {
    int n = blockIdx.x * blockDim.x + threadIdx.x;
    if (n > NN) return;
    int lo = 0, hi = EE;
    while (lo < hi) {
        int mid = (lo + hi) >> 1;
        if (dst[mid] < n) lo = mid + 1; else hi = mid;
    }
    g_row_ptr[n] = lo;
}

// ---------------- K1: relation normalization + per-relation scalars --------
__global__ void k_rel(const float* __restrict__ rel_emb,
                      const float* __restrict__ attn_e,
                      const float* __restrict__ attn_r) {
    int warp = (blockIdx.x * blockDim.x + threadIdx.x) >> 5;
    int lane = threadIdx.x & 31;
    if (warp >= RR) return;

    float4 v = {0.f, 0.f, 0.f, 0.f};
    if (lane < D4) v = reinterpret_cast<const float4*>(rel_emb)[warp * D4 + lane];
    float ss = dot4(v, v), dummy = 0.f;
    wred2(ss, dummy);
    float inv = 1.f / fmaxf(sqrtf(ss), 1e-12f);
    v.x *= inv; v.y *= inv; v.z *= inv; v.w *= inv;
    if (lane < D4) g_rel_norm[warp * D4 + lane] = v;

#pragma unroll
    for (int c = 0; c < 4; c++) {   // c = enc*2 + layer
        const float* attn = (c < 2 ? attn_e : attn_r) + (c & 1) * (3 * DD);
        float4 wn = {0.f, 0.f, 0.f, 0.f}, wr = {0.f, 0.f, 0.f, 0.f};
        if (lane < D4) {
            wn = reinterpret_cast<const float4*>(attn + DD)[lane];
            wr = reinterpret_cast<const float4*>(attn + 2 * DD)[lane];
        }
        float dn = dot4(v, wn);
        float dr = dot4(v, wr);
        wred2(dn, dr);
        if (lane == 0) {
            int layer = c & 1;
            if (c < 2) { g_relsc[layer][warp].x = -2.f * dn; g_relsc[layer][warp].y = dr; }
            else       { g_relsc[layer][warp].z = -2.f * dn; g_relsc[layer][warp].w = dr; }
        }
    }
}

// ---------------- K2: initial segment means + tanh + ndot(layer 0) ---------
__global__ void __launch_bounds__(256)
k_init(const float* __restrict__ ent_emb,
       const float* __restrict__ rel_emb,
       const int* __restrict__ src,
       const int* __restrict__ erel,
       const float* __restrict__ attn_e,
       const float* __restrict__ attn_r,
       float* __restrict__ out) {
    int warp = (blockIdx.x * blockDim.x + threadIdx.x) >> 5;
    int lane = threadIdx.x & 31;
    if (warp >= NN) return;
    int beg = g_row_ptr[warp], end = g_row_ptr[warp + 1];
    bool act = lane < D4;

    const float4* ent4 = reinterpret_cast<const float4*>(ent_emb);
    const float4* rel4 = reinterpret_cast<const float4*>(rel_emb);
    float4 aE = {0,0,0,0}, aR = {0,0,0,0};
    float4 bE = {0,0,0,0}, bR = {0,0,0,0};
    int e = beg;
    for (; e + 3 < end; e += 4) {
        int s0 = src[e],   r0 = erel[e];
        int s1 = src[e+1], r1 = erel[e+1];
        int s2 = src[e+2], r2 = erel[e+2];
        int s3 = src[e+3], r3 = erel[e+3];
        if (act) {
            float4 a0 = ent4[s0*D4+lane], c0 = rel4[r0*D4+lane];
            float4 a1 = ent4[s1*D4+lane], c1 = rel4[r1*D4+lane];
            float4 a2 = ent4[s2*D4+lane], c2 = rel4[r2*D4+lane];
            float4 a3 = ent4[s3*D4+lane], c3 = rel4[r3*D4+lane];
            aE.x += a0.x + a1.x; aE.y += a0.y + a1.y; aE.z += a0.z + a1.z; aE.w += a0.w + a1.w;
            bE.x += a2.x + a3.x; bE.y += a2.y + a3.y; bE.z += a2.z + a3.z; bE.w += a2.w + a3.w;
            aR.x += c0.x + c1.x; aR.y += c0.y + c1.y; aR.z += c0.z + c1.z; aR.w += c0.w + c1.w;
            bR.x += c2.x + c3.x; bR.y += c2.y + c3.y; bR.z += c2.z + c3.z; bR.w += c2.w + c3.w;
        }
    }
    for (; e < end; e++) {
        int s0 = src[e], r0 = erel[e];
        if (act) {
            float4 a0 = ent4[s0*D4+lane], c0 = rel4[r0*D4+lane];
            aE.x += a0.x; aE.y += a0.y; aE.z += a0.z; aE.w += a0.w;
            aR.x += c0.x; aR.y += c0.y; aR.z += c0.z; aR.w += c0.w;
        }
    }
    aE.x += bE.x; aE.y += bE.y; aE.z += bE.z; aE.w += bE.w;
    aR.x += bR.x; aR.y += bR.y; aR.z += bR.z; aR.w += bR.w;

    float inv = 1.f / (float)max(end - beg, 1);
    float4 fE, fR;
    fE.x = tanhf(aE.x * inv); fE.y = tanhf(aE.y * inv);
    fE.z = tanhf(aE.z * inv); fE.w = tanhf(aE.w * inv);
    fR.x = tanhf(aR.x * inv); fR.y = tanhf(aR.y * inv);
    fR.z = tanhf(aR.z * inv); fR.w = tanhf(aR.w * inv);

    float4* out4 = reinterpret_cast<float4*>(out);
    if (act) {
        g_feat0[warp * FSTR + lane]      = fE;
        g_feat0[warp * FSTR + D4 + lane] = fR;
        out4[warp * 150 + lane]      = fE;
        out4[warp * 150 + 75 + lane] = fR;
    }

    float4 wnE = {0,0,0,0}, wnR = {0,0,0,0};
    if (act) {
        wnE = reinterpret_cast<const float4*>(attn_e + DD)[lane];
        wnR = reinterpret_cast<const float4*>(attn_r + DD)[lane];
    }
    float dE = dot4(fE, wnE);
    float dR = dot4(fR, wnR);
    wred2(dE, dR);
    if (lane == 0) g_nd[0][warp] = make_float2(dE, dR);
}

// ---------------- K3: attention layer, 2 edges/warp in 16-lane groups -----
template <int LAYER>
__global__ void __launch_bounds__(256)
k_layer(const int* __restrict__ src,
        const int* __restrict__ erel,
        const float* __restrict__ attn_e,
        const float* __restrict__ attn_r,
        float* __restrict__ out) {
    int warp = (blockIdx.x * blockDim.x + threadIdx.x) >> 5;
    int lane = threadIdx.x & 31;
    if (warp >= NN) return;
    int beg = g_row_ptr[warp], end = g_row_ptr[warp + 1];
    int len = end - beg;

    const float4* __restrict__ feat = (LAYER == 0) ? g_feat0 : g_feat1;
    const float2* __restrict__ nd   = g_nd[LAYER];
    const float4* __restrict__ rsc  = g_relsc[LAYER];

    int gid = lane >> 4;          // edge slot within iteration
    int k   = lane & 15;          // f4 chunk: covers f4 k and (if k<9) k+16
    bool hi = k < (D4 - 16);      // chunk-1 validity (9 chunks: 16..24)

    float ZE = 0.f, ZR = 0.f;
    float4 accE0 = {0,0,0,0}, accE1 = {0,0,0,0};
    float4 accR0 = {0,0,0,0}, accR1 = {0,0,0,0};
    const float4 z4 = {0.f, 0.f, 0.f, 0.f};

    int niter = (len + 1) >> 1;
    for (int it = 0; it < niter; it++) {
        int e = beg + 2 * it + gid;
        bool valid = e < end;
        int ec = valid ? e : end - 1;
        int s = src[ec], r = erel[ec];

        const float4* fr = feat + (size_t)s * FSTR;
        const float4* rr = g_rel_norm + r * D4;
        float4 fE0 = fr[k],      fR0 = fr[D4 + k],      rv0 = rr[k];
        float4 fE1 = hi ? fr[16 + k]       : z4;
        float4 fR1 = hi ? fr[D4 + 16 + k]  : z4;
        float4 rv1 = hi ? rr[16 + k]       : z4;
        float2 ndv = nd[s];
        float4 sc  = rsc[r];

        float pE = dot4(fE0, rv0) + dot4(fE1, rv1);
        float pR = dot4(fR0, rv0) + dot4(fR1, rv1);
#pragma unroll
        for (int o = 1; o <= 8; o <<= 1) {
            pE += __shfl_xor_sync(0xffffffffu, pE, o);
            pR += __shfl_xor_sync(0xffffffffu, pR, o);
        }

        float wE = valid ? __expf(ndv.x + fmaf(pE, sc.x, sc.y)) : 0.f;
        float wR = valid ? __expf(ndv.y + fmaf(pR, sc.z, sc.w)) : 0.f;
        ZE += wE; ZR += wR;
        float bE = 2.f * wE * pE, bR = 2.f * wR * pR;

        accE0.x = fmaf(wE, fE0.x, fmaf(-bE, rv0.x, accE0.x));
        accE0.y = fmaf(wE, fE0.y, fmaf(-bE, rv0.y, accE0.y));
        accE0.z = fmaf(wE, fE0.z, fmaf(-bE, rv0.z, accE0.z));
        accE0.w = fmaf(wE, fE0.w, fmaf(-bE, rv0.w, accE0.w));
        accE1.x = fmaf(wE, fE1.x, fmaf(-bE, rv1.x, accE1.x));
        accE1.y = fmaf(wE, fE1.y, fmaf(-bE, rv1.y, accE1.y));
        accE1.z = fmaf(wE, fE1.z, fmaf(-bE, rv1.z, accE1.z));
        accE1.w = fmaf(wE, fE1.w, fmaf(-bE, rv1.w, accE1.w));
        accR0.x = fmaf(wR, fR0.x, fmaf(-bR, rv0.x, accR0.x));
        accR0.y = fmaf(wR, fR0.y, fmaf(-bR, rv0.y, accR0.y));
        accR0.z = fmaf(wR, fR0.z, fmaf(-bR, rv0.z, accR0.z));
        accR0.w = fmaf(wR, fR0.w, fmaf(-bR, rv0.w, accR0.w));
        accR1.x = fmaf(wR, fR1.x, fmaf(-bR, rv1.x, accR1.x));
        accR1.y = fmaf(wR, fR1.y, fmaf(-bR, rv1.y, accR1.y));
        accR1.z = fmaf(wR, fR1.z, fmaf(-bR, rv1.z, accR1.z));
        accR1.w = fmaf(wR, fR1.w, fmaf(-bR, rv1.w, accR1.w));
    }

    // cross-group combine (once per node)
    ZE += __shfl_xor_sync(0xffffffffu, ZE, 16);
    ZR += __shfl_xor_sync(0xffffffffu, ZR, 16);
    accE0.x += __shfl_xor_sync(0xffffffffu, accE0.x, 16);
    accE0.y += __shfl_xor_sync(0xffffffffu, accE0.y, 16);
    accE0.z += __shfl_xor_sync(0xffffffffu, accE0.z, 16);
    accE0.w += __shfl_xor_sync(0xffffffffu, accE0.w, 16);
    accE1.x += __shfl_xor_sync(0xffffffffu, accE1.x, 16);
    accE1.y += __shfl_xor_sync(0xffffffffu, accE1.y, 16);
    accE1.z += __shfl_xor_sync(0xffffffffu, accE1.z, 16);
    accE1.w += __shfl_xor_sync(0xffffffffu, accE1.w, 16);
    accR0.x += __shfl_xor_sync(0xffffffffu, accR0.x, 16);
    accR0.y += __shfl_xor_sync(0xffffffffu, accR0.y, 16);
    accR0.z += __shfl_xor_sync(0xffffffffu, accR0.z, 16);
    accR0.w += __shfl_xor_sync(0xffffffffu, accR0.w, 16);
    accR1.x += __shfl_xor_sync(0xffffffffu, accR1.x, 16);
    accR1.y += __shfl_xor_sync(0xffffffffu, accR1.y, 16);
    accR1.z += __shfl_xor_sync(0xffffffffu, accR1.z, 16);
    accR1.w += __shfl_xor_sync(0xffffffffu, accR1.w, 16);

    float4 oE0 = {0,0,0,0}, oE1 = {0,0,0,0}, oR0 = {0,0,0,0}, oR1 = {0,0,0,0};
    if (len > 0) {
        float izE = 1.f / ZE, izR = 1.f / ZR;
        oE0.x = tanhf(accE0.x * izE); oE0.y = tanhf(accE0.y * izE);
        oE0.z = tanhf(accE0.z * izE); oE0.w = tanhf(accE0.w * izE);
        oE1.x = tanhf(accE1.x * izE); oE1.y = tanhf(accE1.y * izE);
        oE1.z = tanhf(accE1.z * izE); oE1.w = tanhf(accE1.w * izE);
        oR0.x = tanhf(accR0.x * izR); oR0.y = tanhf(accR0.y * izR);
        oR0.z = tanhf(accR0.z * izR); oR0.w = tanhf(accR0.w * izR);
        oR1.x = tanhf(accR1.x * izR); oR1.y = tanhf(accR1.y * izR);
        oR1.z = tanhf(accR1.z * izR); oR1.w = tanhf(accR1.w * izR);
    }

    // lane l writes output f4 index l: group-0 lanes use chunk0 (f4 k=lane),
    // group-1 lanes use chunk1 (f4 lane = 16 + k)
    float4 myE = gid ? oE1 : oE0;
    float4 myR = gid ? oR1 : oR0;

    float4* out4 = reinterpret_cast<float4*>(out);
    if (lane < D4) {
        out4[warp * 150 + (LAYER + 1) * D4 + lane]      = myE;
        out4[warp * 150 + 75 + (LAYER + 1) * D4 + lane] = myR;
        if (LAYER == 0) {
            g_feat1[warp * FSTR + lane]      = myE;
            g_feat1[warp * FSTR + D4 + lane] = myR;
        }
    }
    if (LAYER == 0) {
        // ndot for layer 1 (chunk-1 values beyond f4 24 are zero by construction)
        const float4* wnE4 = reinterpret_cast<const float4*>(attn_e + 3 * DD + DD);
        const float4* wnR4 = reinterpret_cast<const float4*>(attn_r + 3 * DD + DD);
        float dE = dot4(oE0, wnE4[k]) + (hi ? dot4(oE1, wnE4[16 + k]) : 0.f);
        float dR = dot4(oR0, wnR4[k]) + (hi ? dot4(oR1, wnR4[16 + k]) : 0.f);
#pragma unroll
        for (int o = 1; o <= 8; o <<= 1) {
            dE += __shfl_xor_sync(0xffffffffu, dE, o);
            dR += __shfl_xor_sync(0xffffffffu, dR, o);
        }
        if (lane == 0) g_nd[1][warp] = make_float2(dE, dR);
    }
}

// ---------------------------------------------------------------------------
extern "C" void kernel_launch(void* const* d_in, const int* in_sizes, int n_in,
                              void* d_out, int out_size) {
    const float* ent_emb = (const float*)d_in[0];
    const float* rel_emb = (const float*)d_in[1];
    const float* attn_e  = (const float*)d_in[2];
    const float* attn_r  = (const float*)d_in[3];
    const int*   src     = (const int*)d_in[4];
    const int*   dst     = (const int*)d_in[5];
    const int*   erel    = (const int*)d_in[6];
    float* out = (float*)d_out;

    k_rowptr<<<(NN + 1 + 255) / 256, 256>>>(dst);
    k_rel<<<(RR * 32 + 255) / 256, 256>>>(rel_emb, attn_e, attn_r);
    k_init<<<(NN * 32) / 256, 256>>>(ent_emb, rel_emb, src, erel,
                                     attn_e, attn_r, out);
    k_layer<0><<<(NN * 32) / 256, 256>>>(src, erel, attn_e, attn_r, out);
    k_layer<1><<<(NN * 32) / 256, 256>>>(src, erel, attn_e, attn_r, out);
}